// round 9
// baseline (speedup 1.0000x reference)
#include <cuda_runtime.h>
#include <cstdint>

// MonarchOutProjection:
//   h2[t][m][q]   = sum_k L[m][q][k] * x[t][32k+m]
//   out[t][32p+q] = sum_m R[q][p][m] * h2[t][m][q]
//
// R6 design (LSU-minimizing):
//  - grid (74,2): q-half split (16 q/CTA), 148 persistent CTAs = 1 wave.
//  - Tile = 32 tokens (16 f32x2 pairs). 512 threads / 16 warps.
//  - Stage1: lane=m. Warp (qg=w>>3, pg=w&7): q in [8qg,8qg+8), pairs {2pg,2pg+1}.
//    x loaded DIRECTLY from global into registers (double-buffered 4-k chunks);
//    no x smem at all. wf/ffma2 = 1/2 + 2/8 = 0.75.
//  - Stage2: warp w owns local q=w, lane=p. R[q][p][m] cached in 64 regs/tile
//    (32 LDS amortized over 512 ffma2); h2 read as float4 lane-broadcasts
//    (1 wf per 2 ffma2). Two half-passes (8 pairs each) so the outs staging
//    fits smem. wf/ffma2 ~ 0.56.
//  - smem: Ls 64KB [q][k][m] + Rs 64KB [q][m][p] + h2 64KB [q][pair][m]f32x2
//    + outs 34.8KB [16t][p*17+q]  = 231424 B.

#define THREADS 512
#define GRIDX   74
#define TPT     32

#define OFF_LS   0
#define OFF_RS   16384
#define OFF_H2   32768      // float2[16q][16pair][32m] = 16384 floats
#define OFF_OUT  49152      // outs[16t][544]           =  8704 floats
#define SMEM_FLOATS 57856
#define SMEM_BYTES  (SMEM_FLOATS * 4)   // 231424 B

typedef unsigned long long ull;

__device__ __forceinline__ ull pack2(float v) {
    ull r; asm("mov.b64 %0, {%1, %1};" : "=l"(r) : "f"(v)); return r;
}
__device__ __forceinline__ ull packpair(float a, float b) {
    ull r; asm("mov.b64 %0, {%1, %2};" : "=l"(r) : "f"(a), "f"(b)); return r;
}
__device__ __forceinline__ ull ffma2(ull a, ull b, ull c) {
    ull d; asm("fma.rn.f32x2 %0, %1, %2, %3;" : "=l"(d) : "l"(a), "l"(b), "l"(c));
    return d;
}
__device__ __forceinline__ void unpack2(ull v, float& lo, float& hi) {
    asm("mov.b64 {%0, %1}, %2;" : "=f"(lo), "=f"(hi) : "l"(v));
}

__global__ __launch_bounds__(THREADS, 1)
void monarch_kernel(const float* __restrict__ x,
                    const float* __restrict__ Lg,
                    const float* __restrict__ Rg,
                    float* __restrict__ out,
                    int ntiles)
{
    extern __shared__ float sm[];
    float*  Ls   = sm + OFF_LS;                 // [q*1024 + k*32 + m]
    float*  Rs   = sm + OFF_RS;                 // [q*1024 + m*32 + p]
    float2* h2   = (float2*)(sm + OFF_H2);      // [q*512 + pair*32 + m]
    float*  outs = sm + OFF_OUT;                // [t*544 + p*17 + q]

    const int tid  = threadIdx.x;
    const int w    = tid >> 5;
    const int lane = tid & 31;
    const int qg   = w >> 3;        // q in [8qg, 8qg+8)
    const int pg   = w & 7;         // pairs {2pg, 2pg+1} -> tokens [4pg, 4pg+4)
    const int qb   = blockIdx.y * 16;

    // ---- one-time weight staging (conflicts here are amortized away) ----
    for (int j = tid; j < 16384; j += THREADS) {
        int m = j >> 9, r = j & 511;            // r = q*32 + k
        Ls[(r >> 5) * 1024 + (r & 31) * 32 + m] = Lg[m * 1024 + qb * 32 + r];
    }
    for (int j = tid; j < 16384; j += THREADS) {
        int q = j >> 10, r = j & 1023;          // r = p*32 + m
        Rs[q * 1024 + (r & 31) * 32 + (r >> 5)] = Rg[(qb + q) * 1024 + r];
    }
    __syncthreads();

    int tile = blockIdx.x;

    // ---- register x double buffer: xr[buf][tok*4+kk] ----
    float xr[2][16];
    {
        int pt = (tile < ntiles) ? tile : 0;
        const float* pb = x + (size_t)(pt * TPT + 4 * pg) * 1024 + lane;
        #pragma unroll
        for (int t = 0; t < 4; t++)
            #pragma unroll
            for (int kk = 0; kk < 4; kk++)
                xr[0][t * 4 + kk] = pb[t * 1024 + kk * 32];
    }

    for (; tile < ntiles; tile += GRIDX) {
        // ===================== stage 1 =====================
        ull acc[8][2];
        #pragma unroll
        for (int qs = 0; qs < 8; qs++) { acc[qs][0] = 0ull; acc[qs][1] = 0ull; }

        const float* Lbase = Ls + qg * 8192 + lane;

        #pragma unroll 2
        for (int c = 0; c < 8; c++) {
            const int cb = c & 1;
            // prefetch next chunk (or next tile's chunk 0) — branchless clamp
            {
                int  ptile = (c < 7) ? tile : (tile + GRIDX);
                int  pk    = (c < 7) ? (c + 1) * 4 : 0;
                bool ok    = ptile < ntiles;
                int  st    = ok ? ptile : 0;
                const float* pb = x + (size_t)(st * TPT + 4 * pg) * 1024
                                    + pk * 32 + lane;
                #pragma unroll
                for (int t = 0; t < 4; t++)
                    #pragma unroll
                    for (int kk = 0; kk < 4; kk++)
                        xr[cb ^ 1][t * 4 + kk] = pb[t * 1024 + kk * 32];
            }
            // compute on chunk c
            #pragma unroll
            for (int kk = 0; kk < 4; kk++) {
                const int k = c * 4 + kk;
                ull v0 = packpair(xr[cb][0 * 4 + kk], xr[cb][1 * 4 + kk]);
                ull v1 = packpair(xr[cb][2 * 4 + kk], xr[cb][3 * 4 + kk]);
                const float* Lp = Lbase + k * 32;
                #pragma unroll
                for (int qs = 0; qs < 8; qs++) {
                    ull Lq = pack2(Lp[qs * 1024]);
                    acc[qs][0] = ffma2(Lq, v0, acc[qs][0]);
                    acc[qs][1] = ffma2(Lq, v1, acc[qs][1]);
                }
            }
        }

        // h2[q][pair][m] <- acc   (8B STS, conflict-free)
        #pragma unroll
        for (int qs = 0; qs < 8; qs++)
            #pragma unroll
            for (int pr = 0; pr < 2; pr++)
                *(ull*)&h2[((qg * 8 + qs) * 16 + 2 * pg + pr) * 32 + lane] =
                    acc[qs][pr];
        __syncthreads();                        // sync1: h2 complete

        // ===================== stage 2 =====================
        // R cache: 32 ull regs, reloaded per tile (cheap: 32 wf / 512 ffma2)
        ull rr[32];
        {
            const float* Rp = Rs + w * 1024 + lane;
            #pragma unroll
            for (int m = 0; m < 32; m++) rr[m] = pack2(Rp[m * 32]);
        }
        const float4* hq = (const float4*)(h2 + w * 512);  // [ (j*32+m)>>1 ]

        // ---- half A: pairs 0..7 (tokens 0..15) ----
        {
            ull a2[8];
            #pragma unroll
            for (int j = 0; j < 8; j++) a2[j] = 0ull;
            #pragma unroll
            for (int m = 0; m < 32; m += 2) {
                #pragma unroll
                for (int j = 0; j < 8; j++) {
                    float4 hh = hq[(j * 32 + m) >> 1];
                    ull h0 = packpair(hh.x, hh.y);
                    ull h1 = packpair(hh.z, hh.w);
                    a2[j] = ffma2(rr[m],     h0, a2[j]);
                    a2[j] = ffma2(rr[m + 1], h1, a2[j]);
                }
            }
            #pragma unroll
            for (int j = 0; j < 8; j++) {
                float f0, f1; unpack2(a2[j], f0, f1);
                outs[(2 * j)     * 544 + lane * 17 + w] = f0;
                outs[(2 * j + 1) * 544 + lane * 17 + w] = f1;
            }
        }
        __syncthreads();                        // sync2: outsA complete

        // writeout A: tokens tile*32 + [0,16)
        {
            const size_t gb = (size_t)tile * TPT * 1024 + qb;
            #pragma unroll
            for (int i = 0; i < 16; i++) {
                int lin = tid + i * THREADS;
                int q = lin & 15, p = (lin >> 4) & 31, t = lin >> 9;
                out[gb + (size_t)t * 1024 + p * 32 + q] =
                    outs[t * 544 + p * 17 + q];
            }
        }
        __syncthreads();                        // sync3: outs reusable

        // ---- half B: pairs 8..15 (tokens 16..31) ----
        {
            ull a2[8];
            #pragma unroll
            for (int j = 0; j < 8; j++) a2[j] = 0ull;
            #pragma unroll
            for (int m = 0; m < 32; m += 2) {
                #pragma unroll
                for (int j = 0; j < 8; j++) {
                    float4 hh = hq[((j + 8) * 32 + m) >> 1];
                    ull h0 = packpair(hh.x, hh.y);
                    ull h1 = packpair(hh.z, hh.w);
                    a2[j] = ffma2(rr[m],     h0, a2[j]);
                    a2[j] = ffma2(rr[m + 1], h1, a2[j]);
                }
            }
            #pragma unroll
            for (int j = 0; j < 8; j++) {
                float f0, f1; unpack2(a2[j], f0, f1);
                outs[(2 * j)     * 544 + lane * 17 + w] = f0;
                outs[(2 * j + 1) * 544 + lane * 17 + w] = f1;
            }
        }
        __syncthreads();                        // sync4: outsB complete

        // writeout B: tokens tile*32 + [16,32)  (overlaps next stage1)
        {
            const size_t gb = (size_t)(tile * TPT + 16) * 1024 + qb;
            #pragma unroll
            for (int i = 0; i < 16; i++) {
                int lin = tid + i * THREADS;
                int q = lin & 15, p = (lin >> 4) & 31, t = lin >> 9;
                out[gb + (size_t)t * 1024 + p * 32 + q] =
                    outs[t * 544 + p * 17 + q];
            }
        }
        // no trailing sync: next conflicting outs write is after next sync1/2.
    }
}

extern "C" void kernel_launch(void* const* d_in, const int* in_sizes, int n_in,
                              void* d_out, int out_size)
{
    const float* x  = (const float*)d_in[0];
    const float* Lg = (const float*)d_in[1];
    const float* Rg = (const float*)d_in[2];
    float* out      = (float*)d_out;

    const int tokens = in_sizes[0] / 1024;   // 32768
    const int ntiles = tokens / TPT;         // 1024

    cudaFuncSetAttribute(monarch_kernel,
                         cudaFuncAttributeMaxDynamicSharedMemorySize, SMEM_BYTES);

    dim3 grid(GRIDX, 2);
    monarch_kernel<<<grid, THREADS, SMEM_BYTES>>>(x, Lg, Rg, out, ntiles);
}